// round 3
// baseline (speedup 1.0000x reference)
#include <cuda_runtime.h>
#include <math.h>

#define N_NODES 40000
#define N_EDGES 640000
#define D 128
#define NLAYERS 3
#define BN_EPS 1e-5
#define STATS_ROWS 250
#define STATS_BLOCKS (N_NODES / STATS_ROWS) /* 160 */
#define GEMM_BM 64
#define GEMM_BLOCKS (N_NODES / GEMM_BM) /* 625 */

// ---------------- scratch (__device__ globals; no allocations allowed) ----------------
__device__ int   g_deg[N_NODES];
__device__ int   g_cur[N_NODES];
__device__ int   g_offs[N_NODES + 1];
__device__ int   g_ssrc[N_EDGES];
__device__ float g_sew[N_EDGES];

__device__ float g_bufA[(size_t)N_NODES * D];  // x (combine out) / z2 (GEMM2 out)
__device__ float g_bufB[(size_t)N_NODES * D];  // y (GEMM1 out)
__device__ float g_hbuf[(size_t)N_NODES * D];  // h between layers

__device__ float g_psum[STATS_BLOCKS * D];
__device__ float g_psq [STATS_BLOCKS * D];
__device__ float g_a[D];
__device__ float g_c[D];

// ---------------- CSR build ----------------
__global__ void k_zero_deg() {
    int i = blockIdx.x * blockDim.x + threadIdx.x;
    if (i < N_NODES) g_deg[i] = 0;
}

__global__ void k_hist(const int* __restrict__ dst) {
    for (int e = blockIdx.x * blockDim.x + threadIdx.x; e < N_EDGES;
         e += gridDim.x * blockDim.x)
        atomicAdd(&g_deg[dst[e]], 1);
}

__global__ void k_scan() {
    __shared__ int sh[1024];
    int t = threadIdx.x;
    const int CH = (N_NODES + 1023) / 1024;  // 40
    int base = t * CH;
    int s = 0;
    for (int i = 0; i < CH; i++) {
        int idx = base + i;
        if (idx < N_NODES) s += g_deg[idx];
    }
    sh[t] = s;
    __syncthreads();
    // Hillis-Steele inclusive scan
    for (int off = 1; off < 1024; off <<= 1) {
        int v = 0;
        if (t >= off) v = sh[t - off];
        __syncthreads();
        sh[t] += v;
        __syncthreads();
    }
    int run = (t == 0) ? 0 : sh[t - 1];
    for (int i = 0; i < CH; i++) {
        int idx = base + i;
        if (idx < N_NODES) {
            g_offs[idx] = run;
            run += g_deg[idx];
            g_cur[idx] = 0;
        }
    }
    if (t == 1023) g_offs[N_NODES] = run;  // t=1023's chunk is empty -> run == total
}

__global__ void k_scatter(const int* __restrict__ src, const int* __restrict__ dst,
                          const float* __restrict__ ew) {
    for (int e = blockIdx.x * blockDim.x + threadIdx.x; e < N_EDGES;
         e += gridDim.x * blockDim.x) {
        int d = dst[e];
        int p = g_offs[d] + atomicAdd(&g_cur[d], 1);
        g_ssrc[p] = src[e];
        g_sew[p]  = ew[e];
    }
}

// ---------------- aggregation + eps self-combine ----------------
// One warp per node; lane owns one float4 (4 features). No float atomics.
__global__ void k_agg(const float* __restrict__ hin, const float* __restrict__ epsl,
                      int layer, float* __restrict__ xout) {
    int gw   = (blockIdx.x * blockDim.x + threadIdx.x) >> 5;
    int lane = threadIdx.x & 31;
    if (gw >= N_NODES) return;
    const float4* h4 = (const float4*)hin;
    float4 acc = make_float4(0.f, 0.f, 0.f, 0.f);
    int beg = g_offs[gw], end = g_offs[gw + 1];
    int e = beg;
    for (; e + 1 < end; e += 2) {
        int s0 = g_ssrc[e], s1 = g_ssrc[e + 1];
        float w0 = g_sew[e], w1 = g_sew[e + 1];
        float4 v0 = h4[(size_t)s0 * 32 + lane];
        float4 v1 = h4[(size_t)s1 * 32 + lane];
        acc.x = fmaf(w0, v0.x, acc.x); acc.y = fmaf(w0, v0.y, acc.y);
        acc.z = fmaf(w0, v0.z, acc.z); acc.w = fmaf(w0, v0.w, acc.w);
        acc.x = fmaf(w1, v1.x, acc.x); acc.y = fmaf(w1, v1.y, acc.y);
        acc.z = fmaf(w1, v1.z, acc.z); acc.w = fmaf(w1, v1.w, acc.w);
    }
    if (e < end) {
        int s0 = g_ssrc[e];
        float w0 = g_sew[e];
        float4 v0 = h4[(size_t)s0 * 32 + lane];
        acc.x = fmaf(w0, v0.x, acc.x); acc.y = fmaf(w0, v0.y, acc.y);
        acc.z = fmaf(w0, v0.z, acc.z); acc.w = fmaf(w0, v0.w, acc.w);
    }
    float ep = 1.f + epsl[layer];
    float4 sf = h4[(size_t)gw * 32 + lane];
    float4 o;
    o.x = fmaf(ep, sf.x, acc.x); o.y = fmaf(ep, sf.y, acc.y);
    o.z = fmaf(ep, sf.z, acc.z); o.w = fmaf(ep, sf.w, acc.w);
    ((float4*)xout)[(size_t)gw * 32 + lane] = o;
}

// ---------------- 40000x128 @ 128x128 fp32 GEMM ----------------
// Block: 64 rows x 128 cols, 256 threads, thread tile 8x4.
// W (K-major [k][n], 64KB) + X tile (64x128, 32KB) in dynamic smem.
// PRO: apply u = relu(g_a[k]*x + g_c[k]) while staging X (BN1+ReLU of previous stage).
// RELUOUT: y = relu(acc + bias).
template <bool PRO, bool RELUOUT>
__global__ void k_gemm(const float* __restrict__ X, const float* __restrict__ W,
                       const float* __restrict__ bias, float* __restrict__ Y) {
    extern __shared__ float sm[];
    float* ws = sm;             // 128*128
    float* xs = sm + D * D;     // 64*128
    int tid = threadIdx.x;

    const float4* W4 = (const float4*)W;
    float4* ws4 = (float4*)ws;
#pragma unroll 4
    for (int i = tid; i < D * D / 4; i += 256) ws4[i] = W4[i];

    int row0 = blockIdx.x * GEMM_BM;
    const float4* X4 = (const float4*)(X + (size_t)row0 * D);
    float4* xs4 = (float4*)xs;
#pragma unroll
    for (int i = tid; i < GEMM_BM * D / 4; i += 256) {
        float4 v = X4[i];
        if (PRO) {
            int k = (i & 31) * 4;
            v.x = fmaxf(fmaf(g_a[k    ], v.x, g_c[k    ]), 0.f);
            v.y = fmaxf(fmaf(g_a[k + 1], v.y, g_c[k + 1]), 0.f);
            v.z = fmaxf(fmaf(g_a[k + 2], v.z, g_c[k + 2]), 0.f);
            v.w = fmaxf(fmaf(g_a[k + 3], v.w, g_c[k + 3]), 0.f);
        }
        xs4[i] = v;
    }
    __syncthreads();

    int ty = tid >> 5;   // 0..7  -> rows ty*8..+7  (whole warp shares ty -> A loads broadcast)
    int tx = tid & 31;   // 0..31 -> cols tx*4..+3  (B float4 loads conflict-free)
    float acc[8][4];
#pragma unroll
    for (int r = 0; r < 8; r++)
#pragma unroll
        for (int c = 0; c < 4; c++) acc[r][c] = 0.f;

    const float* xr = xs + ty * 8 * D;
#pragma unroll 4
    for (int k = 0; k < D; k++) {
        float4 b = *(const float4*)(ws + k * D + tx * 4);
#pragma unroll
        for (int r = 0; r < 8; r++) {
            float a = xr[r * D + k];
            acc[r][0] = fmaf(a, b.x, acc[r][0]);
            acc[r][1] = fmaf(a, b.y, acc[r][1]);
            acc[r][2] = fmaf(a, b.z, acc[r][2]);
            acc[r][3] = fmaf(a, b.w, acc[r][3]);
        }
    }

    float4 bb = *(const float4*)(bias + tx * 4);
#pragma unroll
    for (int r = 0; r < 8; r++) {
        float4 o;
        o.x = acc[r][0] + bb.x; o.y = acc[r][1] + bb.y;
        o.z = acc[r][2] + bb.z; o.w = acc[r][3] + bb.w;
        if (RELUOUT) {
            o.x = fmaxf(o.x, 0.f); o.y = fmaxf(o.y, 0.f);
            o.z = fmaxf(o.z, 0.f); o.w = fmaxf(o.w, 0.f);
        }
        *(float4*)(Y + (size_t)(row0 + ty * 8 + r) * D + tx * 4) = o;
    }
}

// ---------------- deterministic BN column stats ----------------
__global__ void k_stats_part(const float* __restrict__ Y) {
    int c = threadIdx.x;          // 128 threads = one per feature
    int b = blockIdx.x;           // 160 blocks x 250 rows
    int r0 = b * STATS_ROWS;
    float s = 0.f, s2 = 0.f;
    for (int r = r0; r < r0 + STATS_ROWS; r++) {
        float v = Y[(size_t)r * D + c];
        s += v;
        s2 = fmaf(v, v, s2);
    }
    g_psum[b * D + c] = s;
    g_psq [b * D + c] = s2;
}

__global__ void k_stats_final(const float* __restrict__ gamma,
                              const float* __restrict__ beta) {
    int c = threadIdx.x;
    double s = 0.0, s2 = 0.0;
    for (int b = 0; b < STATS_BLOCKS; b++) {
        s  += (double)g_psum[b * D + c];
        s2 += (double)g_psq [b * D + c];
    }
    double m   = s / (double)N_NODES;
    double var = s2 / (double)N_NODES - m * m;
    if (var < 0.0) var = 0.0;
    float inv = (float)(1.0 / sqrt(var + (double)BN_EPS));
    float a = gamma[c] * inv;
    g_a[c] = a;
    g_c[c] = beta[c] - a * (float)m;
}

// ---------------- BN2 + ReLU elementwise ----------------
__global__ void k_bn_relu(const float* __restrict__ Z, float* __restrict__ O) {
    int i = blockIdx.x * blockDim.x + threadIdx.x;
    const int total = N_NODES * D / 4;
    if (i >= total) return;
    float4 v = ((const float4*)Z)[i];
    int k = (i & 31) * 4;
    float4 o;
    o.x = fmaxf(fmaf(g_a[k    ], v.x, g_c[k    ]), 0.f);
    o.y = fmaxf(fmaf(g_a[k + 1], v.y, g_c[k + 1]), 0.f);
    o.z = fmaxf(fmaf(g_a[k + 2], v.z, g_c[k + 2]), 0.f);
    o.w = fmaxf(fmaf(g_a[k + 3], v.w, g_c[k + 3]), 0.f);
    ((float4*)O)[i] = o;
}

// ---------------- launch ----------------
extern "C" void kernel_launch(void* const* d_in, const int* in_sizes, int n_in,
                              void* d_out, int out_size) {
    const float* h    = (const float*)d_in[0];
    const int*   src  = (const int*)d_in[1];
    const int*   dst  = (const int*)d_in[2];
    const float* ew   = (const float*)d_in[3];
    const float* epsl = (const float*)d_in[4];
    const float* W1   = (const float*)d_in[5];
    const float* b1   = (const float*)d_in[6];
    const float* g1   = (const float*)d_in[7];
    const float* bt1  = (const float*)d_in[8];
    const float* W2   = (const float*)d_in[9];
    const float* b2   = (const float*)d_in[10];
    const float* g2   = (const float*)d_in[11];
    const float* bt2  = (const float*)d_in[12];
    float* out = (float*)d_out;

    const size_t smem = (size_t)(D * D + GEMM_BM * D) * sizeof(float);  // 98304 B
    cudaFuncSetAttribute(k_gemm<false, false>,
                         cudaFuncAttributeMaxDynamicSharedMemorySize, (int)smem);
    cudaFuncSetAttribute(k_gemm<true, true>,
                         cudaFuncAttributeMaxDynamicSharedMemorySize, (int)smem);

    void *pA = nullptr, *pB = nullptr, *pH = nullptr;
    cudaGetSymbolAddress(&pA, g_bufA);
    cudaGetSymbolAddress(&pB, g_bufB);
    cudaGetSymbolAddress(&pH, g_hbuf);
    float* bufA = (float*)pA;
    float* bufB = (float*)pB;
    float* bufH = (float*)pH;

    // CSR build (per replay; deterministic work)
    k_zero_deg<<<(N_NODES + 255) / 256, 256>>>();
    k_hist<<<640, 256>>>(dst);
    k_scan<<<1, 1024>>>();
    k_scatter<<<640, 256>>>(src, dst, ew);

    const float* hin = h;
    for (int l = 0; l < NLAYERS; l++) {
        // x = (1+eps)*h + scatter-sum(ew * h[src])
        k_agg<<<N_NODES * 32 / 256, 256>>>(hin, epsl, l, bufA);
        // y = x @ W1 + b1
        k_gemm<false, false><<<GEMM_BLOCKS, 256, smem>>>(bufA, W1 + l * D * D,
                                                         b1 + l * D, bufB);
        // BN1 params
        k_stats_part<<<STATS_BLOCKS, D>>>(bufB);
        k_stats_final<<<1, D>>>(g1 + l * D, bt1 + l * D);
        // z2 = relu( relu(bn1(y)) @ W2 + b2 )   (bn1+relu fused into X staging)
        k_gemm<true, true><<<GEMM_BLOCKS, 256, smem>>>(bufB, W2 + l * D * D,
                                                       b2 + l * D, bufA);
        // BN2 params
        k_stats_part<<<STATS_BLOCKS, D>>>(bufA);
        k_stats_final<<<1, D>>>(g2 + l * D, bt2 + l * D);
        // h = relu(bn2(z2))
        float* o = (l == NLAYERS - 1) ? out : bufH;
        k_bn_relu<<<N_NODES * D / 4 / 256, 256>>>(bufA, o);
        hin = bufH;
    }
}

// round 4
// speedup vs baseline: 1.2687x; 1.2687x over previous
#include <cuda_runtime.h>
#include <math.h>

#define N_NODES 40000
#define N_EDGES 640000
#define D 128
#define NLAYERS 3
#define BN_EPS 1e-5
#define GEMM_BM 64
#define GEMM_BLOCKS (N_NODES / GEMM_BM) /* 625 */

// ---------------- scratch (__device__ globals; no allocations allowed) ----------------
__device__ int   g_deg[N_NODES];
__device__ int   g_cur[N_NODES];
__device__ int   g_offs[N_NODES + 1];
__device__ int   g_ssrc[N_EDGES];
__device__ float g_sew[N_EDGES];

__device__ float g_bufB[(size_t)N_NODES * D];  // y (GEMM1 out)
__device__ float g_bufZ[(size_t)N_NODES * D];  // z2 (GEMM2 out)
__device__ float g_hbuf[(size_t)N_NODES * D];  // h between layers

__device__ float g_psum[GEMM_BLOCKS * D];
__device__ float g_psq [GEMM_BLOCKS * D];
__device__ float g_a[D];
__device__ float g_c[D];

// ---------------- CSR build ----------------
__global__ void k_zero_deg() {
    int i = blockIdx.x * blockDim.x + threadIdx.x;
    if (i < N_NODES) g_deg[i] = 0;
}

__global__ void k_hist(const int* __restrict__ dst) {
    for (int e = blockIdx.x * blockDim.x + threadIdx.x; e < N_EDGES;
         e += gridDim.x * blockDim.x)
        atomicAdd(&g_deg[dst[e]], 1);
}

__global__ void k_scan() {
    __shared__ int sh[1024];
    int t = threadIdx.x;
    const int CH = (N_NODES + 1023) / 1024;  // 40
    int base = t * CH;
    int s = 0;
    for (int i = 0; i < CH; i++) {
        int idx = base + i;
        if (idx < N_NODES) s += g_deg[idx];
    }
    sh[t] = s;
    __syncthreads();
    for (int off = 1; off < 1024; off <<= 1) {
        int v = 0;
        if (t >= off) v = sh[t - off];
        __syncthreads();
        sh[t] += v;
        __syncthreads();
    }
    int run = (t == 0) ? 0 : sh[t - 1];
    for (int i = 0; i < CH; i++) {
        int idx = base + i;
        if (idx < N_NODES) {
            g_offs[idx] = run;
            run += g_deg[idx];
            g_cur[idx] = 0;
        }
    }
    if (t == 1023) g_offs[N_NODES] = run;
}

__global__ void k_scatter(const int* __restrict__ src, const int* __restrict__ dst,
                          const float* __restrict__ ew) {
    for (int e = blockIdx.x * blockDim.x + threadIdx.x; e < N_EDGES;
         e += gridDim.x * blockDim.x) {
        int d = dst[e];
        int p = g_offs[d] + atomicAdd(&g_cur[d], 1);
        g_ssrc[p] = src[e];
        g_sew[p]  = ew[e];
    }
}

// ---------------- fused GEMM: [stage X] -> 64x128 @ 128x128 -> [bias/ReLU] -> [stats]
// Block: 64 rows x 128 cols, 256 threads, thread tile 8x4.
// GATHER:  X tile = (1+eps)*h[node] + sum_e ew*h[src]  (CSR gather; X := h)
// PRO:     X tile = relu(g_a*X + g_c)                  (BN1+ReLU folded into staging)
// RELUOUT: out = relu(acc + bias)
// Always: per-block column sum / sumsq -> g_psum/g_psq[blockIdx] (deterministic)
template <bool GATHER, bool PRO, bool RELUOUT>
__global__ void k_gemm(const float* __restrict__ X, const float* __restrict__ W,
                       const float* __restrict__ bias,
                       const float* __restrict__ epsl, int layer,
                       float* __restrict__ Y) {
    extern __shared__ float sm[];
    float* ws = sm;             // 128*128 W (K-major [k][n])
    float* xs = sm + D * D;     // 64*128 X tile
    __shared__ float red[2][8][D];  // static 8KB for stats reduction

    int tid  = threadIdx.x;
    int wid  = tid >> 5;   // 0..7
    int lane = tid & 31;   // 0..31
    int row0 = blockIdx.x * GEMM_BM;

    // stage W
    const float4* W4 = (const float4*)W;
    float4* ws4 = (float4*)ws;
#pragma unroll 4
    for (int i = tid; i < D * D / 4; i += 256) ws4[i] = W4[i];

    // stage X
    if (GATHER) {
        const float4* h4 = (const float4*)X;
        float ep = 1.f + epsl[layer];
        for (int i = wid; i < GEMM_BM; i += 8) {
            int node = row0 + i;
            int beg = g_offs[node], end = g_offs[node + 1];
            float4 a = make_float4(0.f, 0.f, 0.f, 0.f);
            int e = beg;
            for (; e + 1 < end; e += 2) {
                int   s0 = g_ssrc[e],  s1 = g_ssrc[e + 1];
                float w0 = g_sew[e],   w1 = g_sew[e + 1];
                float4 v0 = h4[(size_t)s0 * 32 + lane];
                float4 v1 = h4[(size_t)s1 * 32 + lane];
                a.x = fmaf(w0, v0.x, a.x); a.y = fmaf(w0, v0.y, a.y);
                a.z = fmaf(w0, v0.z, a.z); a.w = fmaf(w0, v0.w, a.w);
                a.x = fmaf(w1, v1.x, a.x); a.y = fmaf(w1, v1.y, a.y);
                a.z = fmaf(w1, v1.z, a.z); a.w = fmaf(w1, v1.w, a.w);
            }
            if (e < end) {
                int s0 = g_ssrc[e];
                float w0 = g_sew[e];
                float4 v0 = h4[(size_t)s0 * 32 + lane];
                a.x = fmaf(w0, v0.x, a.x); a.y = fmaf(w0, v0.y, a.y);
                a.z = fmaf(w0, v0.z, a.z); a.w = fmaf(w0, v0.w, a.w);
            }
            float4 sf = h4[(size_t)node * 32 + lane];
            a.x = fmaf(ep, sf.x, a.x); a.y = fmaf(ep, sf.y, a.y);
            a.z = fmaf(ep, sf.z, a.z); a.w = fmaf(ep, sf.w, a.w);
            *(float4*)(xs + i * D + lane * 4) = a;
        }
    } else {
        const float4* X4 = (const float4*)(X + (size_t)row0 * D);
        float4* xs4 = (float4*)xs;
#pragma unroll
        for (int i = tid; i < GEMM_BM * D / 4; i += 256) {
            float4 v = X4[i];
            if (PRO) {
                int k = (i & 31) * 4;
                v.x = fmaxf(fmaf(g_a[k    ], v.x, g_c[k    ]), 0.f);
                v.y = fmaxf(fmaf(g_a[k + 1], v.y, g_c[k + 1]), 0.f);
                v.z = fmaxf(fmaf(g_a[k + 2], v.z, g_c[k + 2]), 0.f);
                v.w = fmaxf(fmaf(g_a[k + 3], v.w, g_c[k + 3]), 0.f);
            }
            xs4[i] = v;
        }
    }
    __syncthreads();

    int ty = wid;   // whole warp shares ty -> A smem loads broadcast
    int tx = lane;  // B float4 loads conflict-free
    float acc[8][4];
#pragma unroll
    for (int r = 0; r < 8; r++)
#pragma unroll
        for (int c = 0; c < 4; c++) acc[r][c] = 0.f;

    const float* xr = xs + ty * 8 * D;
#pragma unroll 4
    for (int k = 0; k < D; k += 4) {
        float4 b0 = *(const float4*)(ws + (k    ) * D + tx * 4);
        float4 b1 = *(const float4*)(ws + (k + 1) * D + tx * 4);
        float4 b2 = *(const float4*)(ws + (k + 2) * D + tx * 4);
        float4 b3 = *(const float4*)(ws + (k + 3) * D + tx * 4);
#pragma unroll
        for (int r = 0; r < 8; r++) {
            float4 a = *(const float4*)(xr + r * D + k);
            acc[r][0] = fmaf(a.x, b0.x, acc[r][0]);
            acc[r][1] = fmaf(a.x, b0.y, acc[r][1]);
            acc[r][2] = fmaf(a.x, b0.z, acc[r][2]);
            acc[r][3] = fmaf(a.x, b0.w, acc[r][3]);
            acc[r][0] = fmaf(a.y, b1.x, acc[r][0]);
            acc[r][1] = fmaf(a.y, b1.y, acc[r][1]);
            acc[r][2] = fmaf(a.y, b1.z, acc[r][2]);
            acc[r][3] = fmaf(a.y, b1.w, acc[r][3]);
            acc[r][0] = fmaf(a.z, b2.x, acc[r][0]);
            acc[r][1] = fmaf(a.z, b2.y, acc[r][1]);
            acc[r][2] = fmaf(a.z, b2.z, acc[r][2]);
            acc[r][3] = fmaf(a.z, b2.w, acc[r][3]);
            acc[r][0] = fmaf(a.w, b3.x, acc[r][0]);
            acc[r][1] = fmaf(a.w, b3.y, acc[r][1]);
            acc[r][2] = fmaf(a.w, b3.z, acc[r][2]);
            acc[r][3] = fmaf(a.w, b3.w, acc[r][3]);
        }
    }

    // epilogue: bias (+relu), store, per-thread column partials
    float4 bb = *(const float4*)(bias + tx * 4);
    float s0 = 0.f, s1 = 0.f, s2 = 0.f, s3 = 0.f;
    float q0 = 0.f, q1 = 0.f, q2 = 0.f, q3 = 0.f;
#pragma unroll
    for (int r = 0; r < 8; r++) {
        float4 o;
        o.x = acc[r][0] + bb.x; o.y = acc[r][1] + bb.y;
        o.z = acc[r][2] + bb.z; o.w = acc[r][3] + bb.w;
        if (RELUOUT) {
            o.x = fmaxf(o.x, 0.f); o.y = fmaxf(o.y, 0.f);
            o.z = fmaxf(o.z, 0.f); o.w = fmaxf(o.w, 0.f);
        }
        *(float4*)(Y + (size_t)(row0 + ty * 8 + r) * D + tx * 4) = o;
        s0 += o.x; s1 += o.y; s2 += o.z; s3 += o.w;
        q0 = fmaf(o.x, o.x, q0); q1 = fmaf(o.y, o.y, q1);
        q2 = fmaf(o.z, o.z, q2); q3 = fmaf(o.w, o.w, q3);
    }
    red[0][ty][tx * 4    ] = s0; red[0][ty][tx * 4 + 1] = s1;
    red[0][ty][tx * 4 + 2] = s2; red[0][ty][tx * 4 + 3] = s3;
    red[1][ty][tx * 4    ] = q0; red[1][ty][tx * 4 + 1] = q1;
    red[1][ty][tx * 4 + 2] = q2; red[1][ty][tx * 4 + 3] = q3;
    __syncthreads();
    if (tid < D) {
        float ps = 0.f, pq = 0.f;
#pragma unroll
        for (int j = 0; j < 8; j++) { ps += red[0][j][tid]; pq += red[1][j][tid]; }
        g_psum[blockIdx.x * D + tid] = ps;
        g_psq [blockIdx.x * D + tid] = pq;
    }
}

// ---------------- BN finalize: one block per feature column ----------------
__global__ void k_finalize(const float* __restrict__ gamma,
                           const float* __restrict__ beta) {
    __shared__ double sh[2][256];
    int c = blockIdx.x;    // 0..127
    int t = threadIdx.x;   // 256
    double s = 0.0, q = 0.0;
    for (int b = t; b < GEMM_BLOCKS; b += 256) {
        s += (double)g_psum[b * D + c];
        q += (double)g_psq [b * D + c];
    }
    sh[0][t] = s; sh[1][t] = q;
    __syncthreads();
    for (int o = 128; o > 0; o >>= 1) {
        if (t < o) { sh[0][t] += sh[0][t + o]; sh[1][t] += sh[1][t + o]; }
        __syncthreads();
    }
    if (t == 0) {
        double m   = sh[0][0] / (double)N_NODES;
        double var = sh[1][0] / (double)N_NODES - m * m;
        if (var < 0.0) var = 0.0;
        float inv = (float)(1.0 / sqrt(var + (double)BN_EPS));
        float a = gamma[c] * inv;
        g_a[c] = a;
        g_c[c] = beta[c] - a * (float)m;
    }
}

// ---------------- BN2 + ReLU elementwise ----------------
__global__ void k_bn_relu(const float* __restrict__ Z, float* __restrict__ O) {
    int i = blockIdx.x * blockDim.x + threadIdx.x;
    const int total = N_NODES * D / 4;
    if (i >= total) return;
    float4 v = ((const float4*)Z)[i];
    int k = (i & 31) * 4;
    float4 o;
    o.x = fmaxf(fmaf(g_a[k    ], v.x, g_c[k    ]), 0.f);
    o.y = fmaxf(fmaf(g_a[k + 1], v.y, g_c[k + 1]), 0.f);
    o.z = fmaxf(fmaf(g_a[k + 2], v.z, g_c[k + 2]), 0.f);
    o.w = fmaxf(fmaf(g_a[k + 3], v.w, g_c[k + 3]), 0.f);
    ((float4*)O)[i] = o;
}

// ---------------- launch ----------------
extern "C" void kernel_launch(void* const* d_in, const int* in_sizes, int n_in,
                              void* d_out, int out_size) {
    const float* h    = (const float*)d_in[0];
    const int*   src  = (const int*)d_in[1];
    const int*   dst  = (const int*)d_in[2];
    const float* ew   = (const float*)d_in[3];
    const float* epsl = (const float*)d_in[4];
    const float* W1   = (const float*)d_in[5];
    const float* b1   = (const float*)d_in[6];
    const float* g1   = (const float*)d_in[7];
    const float* bt1  = (const float*)d_in[8];
    const float* W2   = (const float*)d_in[9];
    const float* b2   = (const float*)d_in[10];
    const float* g2   = (const float*)d_in[11];
    const float* bt2  = (const float*)d_in[12];
    float* out = (float*)d_out;

    const size_t smem = (size_t)(D * D + GEMM_BM * D) * sizeof(float);  // 98304 B dyn
    cudaFuncSetAttribute(k_gemm<true, false, false>,
                         cudaFuncAttributeMaxDynamicSharedMemorySize, (int)smem);
    cudaFuncSetAttribute(k_gemm<false, true, true>,
                         cudaFuncAttributeMaxDynamicSharedMemorySize, (int)smem);

    void *pB = nullptr, *pZ = nullptr, *pH = nullptr;
    cudaGetSymbolAddress(&pB, g_bufB);
    cudaGetSymbolAddress(&pZ, g_bufZ);
    cudaGetSymbolAddress(&pH, g_hbuf);
    float* bufB = (float*)pB;
    float* bufZ = (float*)pZ;
    float* bufH = (float*)pH;

    // CSR build (per replay; deterministic work)
    k_zero_deg<<<(N_NODES + 255) / 256, 256>>>();
    k_hist<<<640, 256>>>(dst);
    k_scan<<<1, 1024>>>();
    k_scatter<<<640, 256>>>(src, dst, ew);

    const float* hin = h;
    for (int l = 0; l < NLAYERS; l++) {
        // y = ((1+eps)*h + scatter-sum(ew*h[src])) @ W1 + b1   (+BN1 stats)
        k_gemm<true, false, false><<<GEMM_BLOCKS, 256, smem>>>(
            hin, W1 + l * D * D, b1 + l * D, epsl, l, bufB);
        k_finalize<<<D, 256>>>(g1 + l * D, bt1 + l * D);
        // z2 = relu( relu(bn1(y)) @ W2 + b2 )   (+BN2 stats)
        k_gemm<false, true, true><<<GEMM_BLOCKS, 256, smem>>>(
            bufB, W2 + l * D * D, b2 + l * D, epsl, l, bufZ);
        k_finalize<<<D, 256>>>(g2 + l * D, bt2 + l * D);
        // h = relu(bn2(z2))
        float* o = (l == NLAYERS - 1) ? out : bufH;
        k_bn_relu<<<N_NODES * D / 4 / 256, 256>>>(bufZ, o);
        hin = bufH;
    }
}